// round 5
// baseline (speedup 1.0000x reference)
#include <cuda_runtime.h>
#include <cuda_bf16.h>
#include <math.h>

// Problem constants (fixed by the dataset)
#define Bb   4
#define Ss   2048
#define Dd   512
#define Hh   8
#define DK   64
#define Rr   8
#define TR   16
#define NBH  (Bb*Hh)                // 32
#define NNODES (NBH*Ss)             // 65536
#define NEDGE  (NBH*TR*Ss)          // 1048576

// ---------------- scratch (device globals; no allocation allowed) -------------
__device__ float g_q[NBH*Ss*DK];
__device__ float g_k[NBH*Ss*DK];
__device__ float g_v[NBH*Ss*DK];
__device__ float g_e[NEDGE];
__device__ int   g_cnt[NNODES];
__device__ int   g_off[NBH*(Ss+1)];
__device__ int   g_info[NEDGE];
__device__ float g_val[NEDGE];
__device__ float g_attn[Bb*Ss*Dd];   // row m=b*S+s, col h*64+d

// ======================= small helpers =======================================
__device__ __forceinline__ unsigned su32(const void* p){
    unsigned a;
    asm("{ .reg .u64 t; cvta.to.shared.u64 t, %1; cvt.u32.u64 %0, t; }"
        : "=r"(a) : "l"(p));
    return a;
}
__device__ __forceinline__ unsigned packbf2(float x, float y){
    __nv_bfloat162 t = __floats2bfloat162_rn(x, y);
    return *(unsigned*)&t;
}
__device__ __forceinline__ void sts128(unsigned a, unsigned x, unsigned y,
                                       unsigned z, unsigned w){
    asm volatile("st.shared.v4.b32 [%0], {%1,%2,%3,%4};"
                 :: "r"(a), "r"(x), "r"(y), "r"(z), "r"(w) : "memory");
}
__device__ __forceinline__ void ldmx4(unsigned* r, unsigned addr){
    asm volatile("ldmatrix.sync.aligned.m8n8.x4.shared.b16 {%0,%1,%2,%3}, [%4];"
                 : "=r"(r[0]), "=r"(r[1]), "=r"(r[2]), "=r"(r[3]) : "r"(addr));
}
__device__ __forceinline__ void mma_bf16(float* d, const unsigned* a, const unsigned* b){
    asm volatile(
        "mma.sync.aligned.m16n8k16.row.col.f32.bf16.bf16.f32 "
        "{%0,%1,%2,%3}, {%4,%5,%6,%7}, {%8,%9}, {%0,%1,%2,%3};"
        : "+f"(d[0]), "+f"(d[1]), "+f"(d[2]), "+f"(d[3])
        : "r"(a[0]), "r"(a[1]), "r"(a[2]), "r"(a[3]), "r"(b[0]), "r"(b[1]));
}
// 64-byte rows, 16B-granule XOR swizzle: conflict-free ldmatrix
__device__ __forceinline__ unsigned swz(unsigned row, unsigned kb){
    return row * 64u + ((((kb >> 4) ^ ((row >> 1) & 3u)) << 4) | (kb & 15u));
}
__device__ __forceinline__ void split4(const float4& v, unsigned* hi, unsigned* lo){
    float hx = __bfloat162float(__float2bfloat16(v.x));
    float hy = __bfloat162float(__float2bfloat16(v.y));
    float hz = __bfloat162float(__float2bfloat16(v.z));
    float hw = __bfloat162float(__float2bfloat16(v.w));
    hi[0] = packbf2(hx, hy); hi[1] = packbf2(hz, hw);
    lo[0] = packbf2(v.x - hx, v.y - hy);
    lo[1] = packbf2(v.z - hz, v.w - hw);
}

// ================= tensor-core GEMM: C[m,n]=sum_k A[m,k]*W[n,k]+bias[n] =======
// M=8192, N=512, K=512. BM=128, BN=64, BK=32, 256 thr, 8 warps (4M x 2N),
// warp tile 32x32, 2 CTAs/SM. 3-term bf16 split.
// mode: 0->g_q (qkv layout), 1->g_k, 2->g_v, 3->A=g_attn, C=C_ext flat
#define STG_A_H 0
#define STG_A_L 8192
#define STG_B_H 16384
#define STG_B_L 20480
#define STG_SZ  24576

__global__ __launch_bounds__(256, 2) void gemm_tc(
    const float* __restrict__ A_ext, const float* __restrict__ W,
    const float* __restrict__ bias, float* __restrict__ C_ext, int mode)
{
    extern __shared__ char dsm[];
    const unsigned sbase = su32(dsm);

    const float* A = (mode == 3) ? (const float*)g_attn : A_ext;
    float* dst = (mode == 0) ? g_q : (mode == 1) ? g_k : (mode == 2) ? g_v : C_ext;

    const int tid = threadIdx.x;
    const int wid = tid >> 5, lane = tid & 31;
    const int wm = wid & 3, wn = wid >> 2;
    const int m0 = blockIdx.y * 128, n0 = blockIdx.x * 64;

    // A load: 2 threads/row, each 16 floats. B load: 4 threads/row, each 8 floats.
    const int arow = tid >> 1, ah2 = tid & 1;          // A: bytes ah2*32, 16 floats
    const int brow = tid >> 2, bs4 = tid & 3;          // B: bytes bs4*16, 8 floats
    const float* Aptr = A + (size_t)(m0 + arow) * Dd + ah2 * 16;
    const float* Wptr = W + (size_t)(n0 + brow) * Dd + bs4 * 8;

    float acc[2][4][4];
#pragma unroll
    for (int mt = 0; mt < 2; mt++)
#pragma unroll
        for (int nt = 0; nt < 4; nt++)
#pragma unroll
            for (int i = 0; i < 4; i++) acc[mt][nt][i] = 0.f;

    float4 pa[4], pb[2];
#pragma unroll
    for (int i = 0; i < 4; i++) pa[i] = *(const float4*)(Aptr + i * 4);
#pragma unroll
    for (int i = 0; i < 2; i++) pb[i] = *(const float4*)(Wptr + i * 4);

    // regs -> smem stage 0
    {
        unsigned hi[8], lo[8];
#pragma unroll
        for (int i = 0; i < 4; i++) split4(pa[i], hi + 2*i, lo + 2*i);
        unsigned s0 = sbase + STG_A_H + swz(arow, ah2*32);
        unsigned s1 = sbase + STG_A_H + swz(arow, ah2*32+16);
        sts128(s0, hi[0],hi[1],hi[2],hi[3]); sts128(s1, hi[4],hi[5],hi[6],hi[7]);
        s0 = sbase + STG_A_L + swz(arow, ah2*32); s1 = sbase + STG_A_L + swz(arow, ah2*32+16);
        sts128(s0, lo[0],lo[1],lo[2],lo[3]); sts128(s1, lo[4],lo[5],lo[6],lo[7]);
#pragma unroll
        for (int i = 0; i < 2; i++) split4(pb[i], hi + 2*i, lo + 2*i);
        s0 = sbase + STG_B_H + swz(brow, bs4*16);
        sts128(s0, hi[0],hi[1],hi[2],hi[3]);
        s0 = sbase + STG_B_L + swz(brow, bs4*16);
        sts128(s0, lo[0],lo[1],lo[2],lo[3]);
    }
    __syncthreads();

    for (int c = 0; c < 16; c++) {
        if (c + 1 < 16) {
#pragma unroll
            for (int i = 0; i < 4; i++)
                pa[i] = *(const float4*)(Aptr + (c + 1) * 32 + i * 4);
#pragma unroll
            for (int i = 0; i < 2; i++)
                pb[i] = *(const float4*)(Wptr + (c + 1) * 32 + i * 4);
        }
        const unsigned stg = sbase + (c & 1) * STG_SZ;
#pragma unroll
        for (int ks = 0; ks < 2; ks++) {
            const unsigned kb = ks * 32;
            unsigned ahf[2][4], alf[2][4], bhf[4][2], blf[4][2];
#pragma unroll
            for (int mt = 0; mt < 2; mt++) {
                unsigned r = wm * 32 + mt * 16 + (lane & 15);
                unsigned kbyte = kb + (lane >> 4) * 16;
                ldmx4(ahf[mt], stg + STG_A_H + swz(r, kbyte));
                ldmx4(alf[mt], stg + STG_A_L + swz(r, kbyte));
            }
#pragma unroll
            for (int p = 0; p < 2; p++) {
                unsigned r = wn * 32 + p * 16 + (lane & 7) + ((lane >> 4) << 3);
                unsigned kbyte = kb + ((lane >> 3) & 1) * 16;
                unsigned t[4];
                ldmx4(t, stg + STG_B_H + swz(r, kbyte));
                bhf[2*p][0] = t[0]; bhf[2*p][1] = t[1];
                bhf[2*p+1][0] = t[2]; bhf[2*p+1][1] = t[3];
                ldmx4(t, stg + STG_B_L + swz(r, kbyte));
                blf[2*p][0] = t[0]; blf[2*p][1] = t[1];
                blf[2*p+1][0] = t[2]; blf[2*p+1][1] = t[3];
            }
#pragma unroll
            for (int mt = 0; mt < 2; mt++)
#pragma unroll
                for (int nt = 0; nt < 4; nt++) {
                    mma_bf16(acc[mt][nt], ahf[mt], bhf[nt]);
                    mma_bf16(acc[mt][nt], ahf[mt], blf[nt]);
                    mma_bf16(acc[mt][nt], alf[mt], bhf[nt]);
                }
        }
        if (c + 1 < 16) {
            const unsigned nstg = sbase + ((c + 1) & 1) * STG_SZ;
            unsigned hi[8], lo[8];
#pragma unroll
            for (int i = 0; i < 4; i++) split4(pa[i], hi + 2*i, lo + 2*i);
            unsigned s0 = nstg + STG_A_H + swz(arow, ah2*32);
            unsigned s1 = nstg + STG_A_H + swz(arow, ah2*32+16);
            sts128(s0, hi[0],hi[1],hi[2],hi[3]); sts128(s1, hi[4],hi[5],hi[6],hi[7]);
            s0 = nstg + STG_A_L + swz(arow, ah2*32); s1 = nstg + STG_A_L + swz(arow, ah2*32+16);
            sts128(s0, lo[0],lo[1],lo[2],lo[3]); sts128(s1, lo[4],lo[5],lo[6],lo[7]);
#pragma unroll
            for (int i = 0; i < 2; i++) split4(pb[i], hi + 2*i, lo + 2*i);
            s0 = nstg + STG_B_H + swz(brow, bs4*16);
            sts128(s0, hi[0],hi[1],hi[2],hi[3]);
            s0 = nstg + STG_B_L + swz(brow, bs4*16);
            sts128(s0, lo[0],lo[1],lo[2],lo[3]);
        }
        __syncthreads();
    }

    // -------- epilogue: fragments -> gmem with bias --------
#pragma unroll
    for (int nt = 0; nt < 4; nt++) {
        const int ncol = n0 + wn * 32 + nt * 8 + 2 * (lane & 3);
        const float b0 = bias[ncol], b1 = bias[ncol + 1];
#pragma unroll
        for (int mt = 0; mt < 2; mt++) {
            const int r0 = m0 + wm * 32 + mt * 16 + (lane >> 2);
            float2 v0 = make_float2(acc[mt][nt][0] + b0, acc[mt][nt][1] + b1);
            float2 v1 = make_float2(acc[mt][nt][2] + b0, acc[mt][nt][3] + b1);
            if (mode == 3) {
                *(float2*)(dst + (size_t)r0 * Dd + ncol) = v0;
                *(float2*)(dst + (size_t)(r0 + 8) * Dd + ncol) = v1;
            } else {
                const int h = ncol >> 6, d = ncol & 63;
                int b = r0 >> 11, s = r0 & (Ss - 1);
                *(float2*)(dst + (size_t)(((b * Hh + h) * Ss + s)) * DK + d) = v0;
                b = (r0 + 8) >> 11; s = (r0 + 8) & (Ss - 1);
                *(float2*)(dst + (size_t)(((b * Hh + h) * Ss + s)) * DK + d) = v1;
            }
        }
    }
}

// ---------------- zero counters -------------------------------------------
__global__ void k_zero()
{
    int i = blockIdx.x * 256 + threadIdx.x;
    if (i < NNODES) g_cnt[i] = 0;
}

// ---------------- per-edge score + exp + count -----------------------------
__global__ __launch_bounds__(256) void k_edges(
    const int* __restrict__ snod, const int* __restrict__ enod,
    const float* __restrict__ rq, const float* __restrict__ rk)
{
    int gt = blockIdx.x * 256 + threadIdx.x;
    int e = gt >> 4;
    int sub = gt & 15;
    int s = e & (Ss - 1);
    int j = (e >> 11) & 15;
    int bh = e >> 15;
    int h = bh & (Hh - 1);
    int jm = j & (Rr - 1);
    int nidx = (bh * Rr + jm) * Ss + s;
    int sv = snod[nidx];
    int ev = enod[nidx];
    bool masked = (j == 0) || (sv < 0);
    int s0 = sv < 0 ? 0 : sv;
    int qn = (j < Rr) ? ev : s0;
    int kn = (j < Rr) ? s0 : ev;
    qn &= (Ss - 1); kn &= (Ss - 1);

    const float4 qv  = *(const float4*)&g_q[(size_t)(bh * Ss + qn) * DK + sub * 4];
    const float4 kv  = *(const float4*)&g_k[(size_t)(bh * Ss + kn) * DK + sub * 4];
    const float4 rqv = *(const float4*)&rq[(h * TR + j) * DK + sub * 4];
    const float4 rkv = *(const float4*)&rk[(h * TR + j) * DK + sub * 4];

    float p = qv.x * (kv.x + rkv.x) + rqv.x * kv.x
            + qv.y * (kv.y + rkv.y) + rqv.y * kv.y
            + qv.z * (kv.z + rkv.z) + rqv.z * kv.z
            + qv.w * (kv.w + rkv.w) + rqv.w * kv.w;
#pragma unroll
    for (int off = 8; off; off >>= 1)
        p += __shfl_xor_sync(0xffffffffu, p, off);

    if (sub == 0 && !masked) {
        float exv = __expf(p * (1.0f / 24.0f));
        g_e[e] = exv;
        atomicAdd(&g_cnt[bh * Ss + qn], 1);
    }
}

// ---------------- exclusive scan of per-node counts per (b,h) --------------
__global__ __launch_bounds__(256) void k_scan()
{
    __shared__ int partial[256];
    int bh = blockIdx.x;
    int t = threadIdx.x;
    int base = bh * Ss + t * 8;
    int c[8]; int sum = 0;
#pragma unroll
    for (int i = 0; i < 8; i++) { c[i] = g_cnt[base + i]; sum += c[i]; }
    partial[t] = sum;
    __syncthreads();
    for (int off = 1; off < 256; off <<= 1) {
        int v = (t >= off) ? partial[t - off] : 0;
        __syncthreads();
        partial[t] += v;
        __syncthreads();
    }
    int run = partial[t] - sum;
    int obase = bh * (Ss + 1) + t * 8;
#pragma unroll
    for (int i = 0; i < 8; i++) { g_off[obase + i] = run; run += c[i]; }
    if (t == 255) g_off[bh * (Ss + 1) + Ss] = run;
#pragma unroll
    for (int i = 0; i < 8; i++) g_cnt[base + i] = 0;
}

// ---------------- CSR fill ---------------------------------------------------
__global__ __launch_bounds__(256) void k_fill(
    const int* __restrict__ snod, const int* __restrict__ enod)
{
    int e = blockIdx.x * 256 + threadIdx.x;
    int s = e & (Ss - 1);
    int j = (e >> 11) & 15;
    int bh = e >> 15;
    int jm = j & (Rr - 1);
    int nidx = (bh * Rr + jm) * Ss + s;
    int sv = snod[nidx];
    if (j == 0 || sv < 0) return;
    int ev = enod[nidx];
    int qn = (j < Rr) ? ev : sv;
    int kn = (j < Rr) ? sv : ev;
    qn &= (Ss - 1); kn &= (Ss - 1);
    int pos = g_off[bh * (Ss + 1) + qn] + atomicAdd(&g_cnt[bh * Ss + qn], 1);
    int idx = bh * (TR * Ss) + pos;
    g_info[idx] = kn | (j << 12);
    g_val[idx] = g_e[e];
}

// ---------------- per-node gather + softmax + weighted sum -------------------
__global__ __launch_bounds__(256) void k_aggr(const float* __restrict__ rv)
{
    int w = (blockIdx.x * 256 + threadIdx.x) >> 5;
    int lane = threadIdx.x & 31;
    int bh = w >> 11;
    int n = w & (Ss - 1);
    int h = bh & (Hh - 1), b = bh >> 3;
    int obase = bh * (Ss + 1) + n;
    int beg = g_off[obase], end = g_off[obase + 1];
    float acc0 = 0.f, acc1 = 0.f, ds = 0.f;
    int cbase = bh * (TR * Ss);
    for (int i = beg; i < end; i++) {
        int info = g_info[cbase + i];
        float evv = g_val[cbase + i];
        int kn = info & 0xFFF;
        int j = info >> 12;
        size_t vb = (size_t)(bh * Ss + kn) * DK;
        int rb = (h * TR + j) * DK;
        acc0 += evv * (g_v[vb + lane] + rv[rb + lane]);
        acc1 += evv * (g_v[vb + 32 + lane] + rv[rb + 32 + lane]);
        ds += evv;
    }
    float inv = ds > 0.f ? 1.f / ds : 0.f;
    size_t ob = (size_t)((b * Ss + n) * Hh + h) * DK;
    g_attn[ob + lane] = acc0 * inv;
    g_attn[ob + 32 + lane] = acc1 * inv;
}

// ---------------- launch --------------------------------------------------
#define GEMM_SMEM (2 * STG_SZ)

extern "C" void kernel_launch(void* const* d_in, const int* in_sizes, int n_in,
                              void* d_out, int out_size)
{
    const float* query = (const float*)d_in[0];
    const float* key   = (const float*)d_in[1];
    const float* value = (const float*)d_in[2];
    const int*   snod  = (const int*)d_in[3];
    const int*   enod  = (const int*)d_in[4];
    const float* rel_q = (const float*)d_in[5];
    const float* rel_k = (const float*)d_in[6];
    const float* rel_v = (const float*)d_in[7];
    const float* Wq = (const float*)d_in[8];
    const float* bq = (const float*)d_in[9];
    const float* Wk = (const float*)d_in[10];
    const float* bk = (const float*)d_in[11];
    const float* Wv = (const float*)d_in[12];
    const float* bv = (const float*)d_in[13];
    const float* Wo = (const float*)d_in[14];
    const float* bo = (const float*)d_in[15];
    float* out = (float*)d_out;

    cudaFuncSetAttribute(gemm_tc, cudaFuncAttributeMaxDynamicSharedMemorySize, GEMM_SMEM);

    dim3 gg(Dd / 64, (Bb * Ss) / 128);   // (8, 64) = 512 CTAs

    k_zero<<<NNODES / 256, 256>>>();
    gemm_tc<<<gg, 256, GEMM_SMEM>>>(query, Wq, bq, nullptr, 0);
    gemm_tc<<<gg, 256, GEMM_SMEM>>>(key,   Wk, bk, nullptr, 1);
    gemm_tc<<<gg, 256, GEMM_SMEM>>>(value, Wv, bv, nullptr, 2);
    k_edges<<<(size_t)NEDGE * 16 / 256, 256>>>(snod, enod, rel_q, rel_k);
    k_scan<<<NBH, 256>>>();
    k_fill<<<NEDGE / 256, 256>>>(snod, enod);
    k_aggr<<<NNODES * 32 / 256, 256>>>(rel_v);
    gemm_tc<<<gg, 256, GEMM_SMEM>>>(nullptr, Wo, bo, out, 3);
}